// round 12
// baseline (speedup 1.0000x reference)
#include <cuda_runtime.h>
#include <cuda_bf16.h>

#define BB 16
#define NN 32768
#define CC 64
#define RR 32
#define R3 (RR*RR*RR)
#define EPSF 1e-6f
#define NPART 32     // partial-reduction blocks per batch
#define SCAN_BLKS 32 // scan blocks per batch (each covers 1024 counts)
#define GATHER_BLKS 592   // 148 SMs x 4 resident blocks — zero wave transitions
#define NTILES (BB * (R3 / 32))  // 16384 logical gather tiles

// Scratch (device globals — zero-initialized at load; no allocation allowed)
__device__ __align__(16) int g_cnt[BB * R3];    // points per voxel (re-zeroed by k_gather)
__device__ __align__(16) int g_cursor[BB * R3]; // reorder cursor (ends at start+cnt)
__device__ int   g_idx[BB * NN];        // voxel index per point
__device__ int   g_order[BB * NN];      // point ids grouped by voxel
__device__ float g_part[BB * NPART][3]; // partial coord sums
__device__ int   g_maxsq[BB];           // max squared norm, float bits (>=0)
__device__ int   g_bsum[BB * SCAN_BLKS];// per-scan-block count sums

// Deterministic mean recompute from partials (same order everywhere)
__device__ __forceinline__ void load_mean(int b, float m[3]) {
    float ax = 0.f, ay = 0.f, az = 0.f;
    #pragma unroll 4
    for (int p = 0; p < NPART; p++) {
        ax += g_part[b * NPART + p][0];
        ay += g_part[b * NPART + p][1];
        az += g_part[b * NPART + p][2];
    }
    m[0] = ax / (float)NN; m[1] = ay / (float)NN; m[2] = az / (float)NN;
}

// ---------------------------------------------------------------------------
__global__ void k_mean1(const float* __restrict__ coords) {
    const int bid = blockIdx.x;
    const int b = bid / NPART;
    const int part = bid % NPART;
    const int per = NN / NPART;
    const float* cb = coords + ((size_t)b * NN + (size_t)part * per) * 3;

    if (part == 0 && threadIdx.x == 0) g_maxsq[b] = 0;

    float sx = 0.f, sy = 0.f, sz = 0.f;
    for (int n = threadIdx.x; n < per; n += blockDim.x) {
        sx += cb[n * 3 + 0];
        sy += cb[n * 3 + 1];
        sz += cb[n * 3 + 2];
    }
    #pragma unroll
    for (int off = 16; off; off >>= 1) {
        sx += __shfl_down_sync(0xffffffffu, sx, off);
        sy += __shfl_down_sync(0xffffffffu, sy, off);
        sz += __shfl_down_sync(0xffffffffu, sz, off);
    }
    __shared__ float sh[3][8];
    const int lane = threadIdx.x & 31, w = threadIdx.x >> 5;
    if (lane == 0) { sh[0][w] = sx; sh[1][w] = sy; sh[2][w] = sz; }
    __syncthreads();
    if (threadIdx.x == 0) {
        float ax = 0.f, ay = 0.f, az = 0.f;
        const int nw = blockDim.x >> 5;
        for (int k = 0; k < nw; k++) { ax += sh[0][k]; ay += sh[1][k]; az += sh[2][k]; }
        g_part[bid][0] = ax; g_part[bid][1] = ay; g_part[bid][2] = az;
    }
}

// ---------------------------------------------------------------------------
__global__ void k_maxnorm(const float* __restrict__ coords) {
    const int bid = blockIdx.x;
    const int b = bid / NPART;
    const int part = bid % NPART;
    const int per = NN / NPART;
    const float* cb = coords + ((size_t)b * NN + (size_t)part * per) * 3;

    __shared__ float smean[3];
    if (threadIdx.x < 3) {
        float m[3];
        load_mean(b, m);
        smean[threadIdx.x] = m[threadIdx.x];
    }
    __syncthreads();
    const float mx = smean[0], my = smean[1], mz = smean[2];

    float m = 0.f;
    for (int n = threadIdx.x; n < per; n += blockDim.x) {
        float dx = cb[n * 3 + 0] - mx;
        float dy = cb[n * 3 + 1] - my;
        float dz = cb[n * 3 + 2] - mz;
        m = fmaxf(m, dx * dx + dy * dy + dz * dz);
    }
    #pragma unroll
    for (int off = 16; off; off >>= 1)
        m = fmaxf(m, __shfl_down_sync(0xffffffffu, m, off));
    __shared__ float sh[8];
    const int lane = threadIdx.x & 31, w = threadIdx.x >> 5;
    if (lane == 0) sh[w] = m;
    __syncthreads();
    if (threadIdx.x == 0) {
        const int nw = blockDim.x >> 5;
        for (int k = 0; k < nw; k++) m = fmaxf(m, sh[k]);
        atomicMax(&g_maxsq[b], __float_as_int(m));
    }
}

// ---------------------------------------------------------------------------
__global__ void k_points(const float* __restrict__ coords,
                         float* __restrict__ out_nc, int write_nc) {
    const int t = blockIdx.x * blockDim.x + threadIdx.x;
    const int b = t >> 15;

    __shared__ float smean[3];
    __shared__ float sden;
    if (threadIdx.x < 3) {
        float m[3];
        load_mean(b, m);
        smean[threadIdx.x] = m[threadIdx.x];
        if (threadIdx.x == 0)
            sden = __fmaf_rn(2.f, __fsqrt_rn(__int_as_float(g_maxsq[b])), EPSF);
    }
    __syncthreads();
    const float d = sden;
    const float mx = smean[0], my = smean[1], mz = smean[2];

    const float x = coords[(size_t)t * 3 + 0];
    const float y = coords[(size_t)t * 3 + 1];
    const float z = coords[(size_t)t * 3 + 2];

    const float nx = __fadd_rn(__fdiv_rn(__fsub_rn(x, mx), d), 0.5f);
    const float ny = __fadd_rn(__fdiv_rn(__fsub_rn(y, my), d), 0.5f);
    const float nz = __fadd_rn(__fdiv_rn(__fsub_rn(z, mz), d), 0.5f);

    int vx = __float2int_rn(__fmul_rn(nx, (float)(RR - 1)));
    int vy = __float2int_rn(__fmul_rn(ny, (float)(RR - 1)));
    int vz = __float2int_rn(__fmul_rn(nz, (float)(RR - 1)));
    vx = min(max(vx, 0), RR - 1);
    vy = min(max(vy, 0), RR - 1);
    vz = min(max(vz, 0), RR - 1);

    const int idx = vx * (RR * RR) + vy * RR + vz;
    g_idx[t] = idx;
    atomicAdd(&g_cnt[b * R3 + idx], 1);

    if (write_nc) {
        out_nc[(size_t)t * 3 + 0] = nx;
        out_nc[(size_t)t * 3 + 1] = ny;
        out_nc[(size_t)t * 3 + 2] = nz;
    }
}

// ---------------------------------------------------------------------------
__global__ void k_scan1() {
    const int4* c4 = reinterpret_cast<const int4*>(g_cnt);
    const int4 v = c4[blockIdx.x * 256 + threadIdx.x];
    int s = v.x + v.y + v.z + v.w;
    #pragma unroll
    for (int off = 16; off; off >>= 1)
        s += __shfl_down_sync(0xffffffffu, s, off);
    __shared__ int sh[8];
    const int lane = threadIdx.x & 31, w = threadIdx.x >> 5;
    if (lane == 0) sh[w] = s;
    __syncthreads();
    if (threadIdx.x == 0) {
        int t = 0;
        #pragma unroll
        for (int k = 0; k < 8; k++) t += sh[k];
        g_bsum[blockIdx.x] = t;
    }
}

// ---------------------------------------------------------------------------
__global__ void k_scan3() {
    const int batch = blockIdx.x >> 5;
    const int blk   = blockIdx.x & 31;

    __shared__ int sboff;
    if (threadIdx.x < 32) {
        int v = g_bsum[batch * SCAN_BLKS + threadIdx.x];
        int inc = v;
        #pragma unroll
        for (int off = 1; off < 32; off <<= 1) {
            int u = __shfl_up_sync(0xffffffffu, inc, off);
            if (threadIdx.x >= off) inc += u;
        }
        if (threadIdx.x == blk) sboff = batch * NN + inc - v;
    }

    const int4* c4 = reinterpret_cast<const int4*>(g_cnt);
    const int i4 = blockIdx.x * 256 + threadIdx.x;
    const int4 v = c4[i4];
    const int tsum = v.x + v.y + v.z + v.w;

    const int lane = threadIdx.x & 31, w = threadIdx.x >> 5;
    int inc = tsum;
    #pragma unroll
    for (int off = 1; off < 32; off <<= 1) {
        int u = __shfl_up_sync(0xffffffffu, inc, off);
        if (lane >= off) inc += u;
    }
    __shared__ int wsum[8];
    if (lane == 31) wsum[w] = inc;
    __syncthreads();
    int woff = 0;
    #pragma unroll
    for (int k = 0; k < 8; k++) woff += (k < w) ? wsum[k] : 0;

    int base = sboff + woff + inc - tsum;
    int4 cur;
    cur.x = base;
    cur.y = base + v.x;
    cur.z = cur.y + v.y;
    cur.w = cur.z + v.z;
    reinterpret_cast<int4*>(g_cursor)[i4] = cur;
}

// ---------------------------------------------------------------------------
__global__ void k_reorder() {
    const int t = blockIdx.x * blockDim.x + threadIdx.x;
    const int b = t >> 15;
    const int slot = atomicAdd(&g_cursor[b * R3 + g_idx[t]], 1);
    g_order[slot] = t;
}

// ---------------------------------------------------------------------------
// PERSISTENT fused gather + mean + transpose. 592 resident blocks grid-stride
// over 16384 tiles (no wave transitions). Double-buffered shared tile: ONE
// barrier per tile — after it, warps store tile i while issuing tile i+1's
// loads. Inner accumulation = R11's 4-point predicated pipeline (proven).
// Epilogue re-zeroes g_cnt per tile.
// ---------------------------------------------------------------------------
__global__ void __launch_bounds__(256, 4)
k_gather(const float* __restrict__ features, float* __restrict__ out) {
    __shared__ float sh[2][CC][33];
    const int tx = threadIdx.x;           // 0..7
    const int ty = threadIdx.y;           // 0..31
    const int tid = ty * 8 + tx;
    const int lane = tid & 31;
    const float4* f4 = reinterpret_cast<const float4*>(features);

    int buf = 0;
    for (int tile = blockIdx.x; tile < NTILES; tile += GATHER_BLKS) {
        const int b  = tile >> 10;            // / (R3/32)
        const int v0 = (tile & 1023) * 32;
        const int seg = b * R3 + v0 + ty;

        const int cnt   = g_cnt[seg];
        const int start = g_cursor[seg] - cnt;

        float4 a0 = make_float4(0.f, 0.f, 0.f, 0.f);
        float4 a1 = make_float4(0.f, 0.f, 0.f, 0.f);

        if (cnt > 0) {
            const bool h1 = cnt > 1, h2 = cnt > 2, h3 = cnt > 3;

            const int p0 = g_order[start];
            int p1 = 0, p2 = 0, p3 = 0;
            if (h1) p1 = g_order[start + 1];
            if (h2) p2 = g_order[start + 2];
            if (h3) p3 = g_order[start + 3];

            const size_t o0 = (size_t)p0 * (CC / 4) + tx;
            const size_t o1 = (size_t)p1 * (CC / 4) + tx;
            const size_t o2 = (size_t)p2 * (CC / 4) + tx;
            const size_t o3 = (size_t)p3 * (CC / 4) + tx;
            float4 x1, y1, x2, y2, x3, y3;
            const float4 x0 = __ldcs(&f4[o0]);
            const float4 y0 = __ldcs(&f4[o0 + 8]);
            if (h1) { x1 = __ldcs(&f4[o1]); y1 = __ldcs(&f4[o1 + 8]); }
            if (h2) { x2 = __ldcs(&f4[o2]); y2 = __ldcs(&f4[o2 + 8]); }
            if (h3) { x3 = __ldcs(&f4[o3]); y3 = __ldcs(&f4[o3 + 8]); }

            a0.x = x0.x; a0.y = x0.y; a0.z = x0.z; a0.w = x0.w;
            a1.x = y0.x; a1.y = y0.y; a1.z = y0.z; a1.w = y0.w;
            if (h1) {
                a0.x += x1.x; a0.y += x1.y; a0.z += x1.z; a0.w += x1.w;
                a1.x += y1.x; a1.y += y1.y; a1.z += y1.z; a1.w += y1.w;
            }
            if (h2) {
                a0.x += x2.x; a0.y += x2.y; a0.z += x2.z; a0.w += x2.w;
                a1.x += y2.x; a1.y += y2.y; a1.z += y2.z; a1.w += y2.w;
            }
            if (h3) {
                a0.x += x3.x; a0.y += x3.y; a0.z += x3.z; a0.w += x3.w;
                a1.x += y3.x; a1.y += y3.y; a1.z += y3.z; a1.w += y3.w;
            }
            for (int j = 4; j < cnt; j++) {
                const int p = g_order[start + j];
                const size_t o = (size_t)p * (CC / 4) + tx;
                const float4 xt = __ldcs(&f4[o]);
                const float4 yt = __ldcs(&f4[o + 8]);
                a0.x += xt.x; a0.y += xt.y; a0.z += xt.z; a0.w += xt.w;
                a1.x += yt.x; a1.y += yt.y; a1.z += yt.z; a1.w += yt.w;
            }
        }

        const float inv = 1.0f / (float)max(cnt, 1);
        a0.x *= inv; a0.y *= inv; a0.z *= inv; a0.w *= inv;
        a1.x *= inv; a1.y *= inv; a1.z *= inv; a1.w *= inv;

        sh[buf][tx * 4 + 0][ty] = a0.x;
        sh[buf][tx * 4 + 1][ty] = a0.y;
        sh[buf][tx * 4 + 2][ty] = a0.z;
        sh[buf][tx * 4 + 3][ty] = a0.w;
        sh[buf][(tx + 8) * 4 + 0][ty] = a1.x;
        sh[buf][(tx + 8) * 4 + 1][ty] = a1.y;
        sh[buf][(tx + 8) * 4 + 2][ty] = a1.z;
        sh[buf][(tx + 8) * 4 + 3][ty] = a1.w;
        __syncthreads();   // the ONLY barrier per tile (double buffer)

        #pragma unroll
        for (int r = 0; r < 8; r++) {
            const int c = (tid >> 5) + r * 8;
            __stcs(&out[((size_t)b * CC + c) * R3 + v0 + lane], sh[buf][c][lane]);
        }

        // reset counts for the next replay
        if (tid < 32) g_cnt[b * R3 + v0 + tid] = 0;

        buf ^= 1;
    }
}

// ---------------------------------------------------------------------------
extern "C" void kernel_launch(void* const* d_in, const int* in_sizes, int n_in,
                              void* d_out, int out_size) {
    const float* features = (const float*)d_in[0];
    const float* coords   = (const float*)d_in[1];
    float* out = (float*)d_out;

    const size_t avg_elems = (size_t)BB * CC * R3;
    const size_t nc_elems  = (size_t)BB * NN * 3;
    const int write_nc = ((size_t)out_size >= avg_elems + nc_elems) ? 1 : 0;
    float* out_nc = out + avg_elems;

    k_mean1<<<BB * NPART, 256>>>(coords);
    k_maxnorm<<<BB * NPART, 256>>>(coords);
    k_points<<<BB * NN / 256, 256>>>(coords, out_nc, write_nc);
    k_scan1<<<BB * SCAN_BLKS, 256>>>();
    k_scan3<<<BB * SCAN_BLKS, 256>>>();
    k_reorder<<<BB * NN / 256, 256>>>();
    {
        dim3 block(8, 32);
        k_gather<<<GATHER_BLKS, block>>>(features, out);
    }
}

// round 13
// speedup vs baseline: 1.2229x; 1.2229x over previous
#include <cuda_runtime.h>
#include <cuda_bf16.h>

#define BB 16
#define NN 32768
#define CC 64
#define RR 32
#define R3 (RR*RR*RR)
#define EPSF 1e-6f
#define NPART 32     // partial-reduction blocks per batch
#define SCAN_BLKS 32 // scan blocks per batch (each covers 1024 counts)

// Scratch (device globals — zero-initialized at load; no allocation allowed)
__device__ __align__(16) int g_cnt[BB * R3];    // points per voxel (re-zeroed by k_gather)
__device__ __align__(16) int g_cursor[BB * R3]; // reorder cursor (ends at start+cnt)
__device__ int   g_idx[BB * NN];        // voxel index per point
__device__ int   g_order[BB * NN];      // point ids grouped by voxel
__device__ float g_part[BB * NPART][3]; // partial coord sums
__device__ int   g_maxsq[BB];           // max squared norm, float bits (>=0)
// Padded block sums: each counter on its OWN 128B L2 line (no LTS same-line
// serialization — the R5 failure mode). Reset by k_mean1 each replay.
__device__ int   g_bsum_pad[BB * SCAN_BLKS * 32];

// Deterministic mean recompute from partials (same order everywhere)
__device__ __forceinline__ void load_mean(int b, float m[3]) {
    float ax = 0.f, ay = 0.f, az = 0.f;
    #pragma unroll 4
    for (int p = 0; p < NPART; p++) {
        ax += g_part[b * NPART + p][0];
        ay += g_part[b * NPART + p][1];
        az += g_part[b * NPART + p][2];
    }
    m[0] = ax / (float)NN; m[1] = ay / (float)NN; m[2] = az / (float)NN;
}

// ---------------------------------------------------------------------------
__global__ void k_mean1(const float* __restrict__ coords) {
    const int bid = blockIdx.x;           // 0..511
    const int b = bid / NPART;
    const int part = bid % NPART;
    const int per = NN / NPART;
    const float* cb = coords + ((size_t)b * NN + (size_t)part * per) * 3;

    if (threadIdx.x == 0) {
        g_bsum_pad[bid * 32] = 0;         // one padded counter per block
        if (part == 0) g_maxsq[b] = 0;
    }

    float sx = 0.f, sy = 0.f, sz = 0.f;
    for (int n = threadIdx.x; n < per; n += blockDim.x) {
        sx += cb[n * 3 + 0];
        sy += cb[n * 3 + 1];
        sz += cb[n * 3 + 2];
    }
    #pragma unroll
    for (int off = 16; off; off >>= 1) {
        sx += __shfl_down_sync(0xffffffffu, sx, off);
        sy += __shfl_down_sync(0xffffffffu, sy, off);
        sz += __shfl_down_sync(0xffffffffu, sz, off);
    }
    __shared__ float sh[3][8];
    const int lane = threadIdx.x & 31, w = threadIdx.x >> 5;
    if (lane == 0) { sh[0][w] = sx; sh[1][w] = sy; sh[2][w] = sz; }
    __syncthreads();
    if (threadIdx.x == 0) {
        float ax = 0.f, ay = 0.f, az = 0.f;
        const int nw = blockDim.x >> 5;
        for (int k = 0; k < nw; k++) { ax += sh[0][k]; ay += sh[1][k]; az += sh[2][k]; }
        g_part[bid][0] = ax; g_part[bid][1] = ay; g_part[bid][2] = az;
    }
}

// ---------------------------------------------------------------------------
__global__ void k_maxnorm(const float* __restrict__ coords) {
    const int bid = blockIdx.x;
    const int b = bid / NPART;
    const int part = bid % NPART;
    const int per = NN / NPART;
    const float* cb = coords + ((size_t)b * NN + (size_t)part * per) * 3;

    __shared__ float smean[3];
    if (threadIdx.x < 3) {
        float m[3];
        load_mean(b, m);
        smean[threadIdx.x] = m[threadIdx.x];
    }
    __syncthreads();
    const float mx = smean[0], my = smean[1], mz = smean[2];

    float m = 0.f;
    for (int n = threadIdx.x; n < per; n += blockDim.x) {
        float dx = cb[n * 3 + 0] - mx;
        float dy = cb[n * 3 + 1] - my;
        float dz = cb[n * 3 + 2] - mz;
        m = fmaxf(m, dx * dx + dy * dy + dz * dz);
    }
    #pragma unroll
    for (int off = 16; off; off >>= 1)
        m = fmaxf(m, __shfl_down_sync(0xffffffffu, m, off));
    __shared__ float sh[8];
    const int lane = threadIdx.x & 31, w = threadIdx.x >> 5;
    if (lane == 0) sh[w] = m;
    __syncthreads();
    if (threadIdx.x == 0) {
        const int nw = blockDim.x >> 5;
        for (int k = 0; k < nw; k++) m = fmaxf(m, sh[k]);
        atomicMax(&g_maxsq[b], __float_as_int(m));
    }
}

// ---------------------------------------------------------------------------
// Per-point: normalized coords, voxel index, voxel-count atomic, PLUS the
// padded per-scan-block sum (replaces the k_scan1 launch).
// ---------------------------------------------------------------------------
__global__ void k_points(const float* __restrict__ coords,
                         float* __restrict__ out_nc, int write_nc) {
    const int t = blockIdx.x * blockDim.x + threadIdx.x;
    const int b = t >> 15;

    __shared__ float smean[3];
    __shared__ float sden;
    if (threadIdx.x < 3) {
        float m[3];
        load_mean(b, m);
        smean[threadIdx.x] = m[threadIdx.x];
        if (threadIdx.x == 0)
            sden = __fmaf_rn(2.f, __fsqrt_rn(__int_as_float(g_maxsq[b])), EPSF);
    }
    __syncthreads();
    const float d = sden;
    const float mx = smean[0], my = smean[1], mz = smean[2];

    const float x = coords[(size_t)t * 3 + 0];
    const float y = coords[(size_t)t * 3 + 1];
    const float z = coords[(size_t)t * 3 + 2];

    const float nx = __fadd_rn(__fdiv_rn(__fsub_rn(x, mx), d), 0.5f);
    const float ny = __fadd_rn(__fdiv_rn(__fsub_rn(y, my), d), 0.5f);
    const float nz = __fadd_rn(__fdiv_rn(__fsub_rn(z, mz), d), 0.5f);

    int vx = __float2int_rn(__fmul_rn(nx, (float)(RR - 1)));
    int vy = __float2int_rn(__fmul_rn(ny, (float)(RR - 1)));
    int vz = __float2int_rn(__fmul_rn(nz, (float)(RR - 1)));
    vx = min(max(vx, 0), RR - 1);
    vy = min(max(vy, 0), RR - 1);
    vz = min(max(vz, 0), RR - 1);

    const int idx = vx * (RR * RR) + vy * RR + vz;
    g_idx[t] = idx;
    atomicAdd(&g_cnt[b * R3 + idx], 1);
    // padded block-sum: each counter on its own 128B line
    atomicAdd(&g_bsum_pad[(b * SCAN_BLKS + (idx >> 10)) * 32], 1);

    if (write_nc) {
        out_nc[(size_t)t * 3 + 0] = nx;
        out_nc[(size_t)t * 3 + 1] = ny;
        out_nc[(size_t)t * 3 + 2] = nz;
    }
}

// ---------------------------------------------------------------------------
// Scan (fused): each block warp-scans its batch's 32 padded block sums for
// its own offset, then block-local exclusive scan of 1024 counts -> g_cursor.
// ---------------------------------------------------------------------------
__global__ void k_scan3() {
    const int batch = blockIdx.x >> 5;
    const int blk   = blockIdx.x & 31;

    __shared__ int sboff;
    if (threadIdx.x < 32) {
        int v = g_bsum_pad[(batch * SCAN_BLKS + threadIdx.x) * 32];
        int inc = v;
        #pragma unroll
        for (int off = 1; off < 32; off <<= 1) {
            int u = __shfl_up_sync(0xffffffffu, inc, off);
            if (threadIdx.x >= off) inc += u;
        }
        if (threadIdx.x == blk) sboff = batch * NN + inc - v;
    }

    const int4* c4 = reinterpret_cast<const int4*>(g_cnt);
    const int i4 = blockIdx.x * 256 + threadIdx.x;
    const int4 v = c4[i4];
    const int tsum = v.x + v.y + v.z + v.w;

    const int lane = threadIdx.x & 31, w = threadIdx.x >> 5;
    int inc = tsum;
    #pragma unroll
    for (int off = 1; off < 32; off <<= 1) {
        int u = __shfl_up_sync(0xffffffffu, inc, off);
        if (lane >= off) inc += u;
    }
    __shared__ int wsum[8];
    if (lane == 31) wsum[w] = inc;
    __syncthreads();
    int woff = 0;
    #pragma unroll
    for (int k = 0; k < 8; k++) woff += (k < w) ? wsum[k] : 0;

    int base = sboff + woff + inc - tsum;
    int4 cur;
    cur.x = base;
    cur.y = base + v.x;
    cur.z = cur.y + v.y;
    cur.w = cur.z + v.z;
    reinterpret_cast<int4*>(g_cursor)[i4] = cur;
}

// ---------------------------------------------------------------------------
__global__ void k_reorder() {
    const int t = blockIdx.x * blockDim.x + threadIdx.x;
    const int b = t >> 15;
    const int slot = atomicAdd(&g_cursor[b * R3 + g_idx[t]], 1);
    g_order[slot] = t;
}

// ---------------------------------------------------------------------------
// Fused gather + mean + transpose — EXACT R11 version (best known: 98.4us).
// 4-point predicated pipelined head, rare scalar tail, launch_bounds(256,4).
// ---------------------------------------------------------------------------
__global__ void __launch_bounds__(256, 4)
k_gather(const float* __restrict__ features, float* __restrict__ out) {
    const int b  = blockIdx.y;
    const int v0 = blockIdx.x * 32;
    const int tx = threadIdx.x;           // 0..7
    const int ty = threadIdx.y;           // 0..31
    const int seg = b * R3 + v0 + ty;

    const int cnt   = g_cnt[seg];
    const int start = g_cursor[seg] - cnt;
    const float4* f4 = reinterpret_cast<const float4*>(features);

    float4 a0 = make_float4(0.f, 0.f, 0.f, 0.f);
    float4 a1 = make_float4(0.f, 0.f, 0.f, 0.f);

    if (cnt > 0) {
        const bool h1 = cnt > 1, h2 = cnt > 2, h3 = cnt > 3;

        const int p0 = g_order[start];
        int p1 = 0, p2 = 0, p3 = 0;
        if (h1) p1 = g_order[start + 1];
        if (h2) p2 = g_order[start + 2];
        if (h3) p3 = g_order[start + 3];

        const size_t o0 = (size_t)p0 * (CC / 4) + tx;
        const size_t o1 = (size_t)p1 * (CC / 4) + tx;
        const size_t o2 = (size_t)p2 * (CC / 4) + tx;
        const size_t o3 = (size_t)p3 * (CC / 4) + tx;
        float4 x1, y1, x2, y2, x3, y3;
        const float4 x0 = __ldcs(&f4[o0]);
        const float4 y0 = __ldcs(&f4[o0 + 8]);
        if (h1) { x1 = __ldcs(&f4[o1]); y1 = __ldcs(&f4[o1 + 8]); }
        if (h2) { x2 = __ldcs(&f4[o2]); y2 = __ldcs(&f4[o2 + 8]); }
        if (h3) { x3 = __ldcs(&f4[o3]); y3 = __ldcs(&f4[o3 + 8]); }

        a0.x = x0.x; a0.y = x0.y; a0.z = x0.z; a0.w = x0.w;
        a1.x = y0.x; a1.y = y0.y; a1.z = y0.z; a1.w = y0.w;
        if (h1) {
            a0.x += x1.x; a0.y += x1.y; a0.z += x1.z; a0.w += x1.w;
            a1.x += y1.x; a1.y += y1.y; a1.z += y1.z; a1.w += y1.w;
        }
        if (h2) {
            a0.x += x2.x; a0.y += x2.y; a0.z += x2.z; a0.w += x2.w;
            a1.x += y2.x; a1.y += y2.y; a1.z += y2.z; a1.w += y2.w;
        }
        if (h3) {
            a0.x += x3.x; a0.y += x3.y; a0.z += x3.z; a0.w += x3.w;
            a1.x += y3.x; a1.y += y3.y; a1.z += y3.z; a1.w += y3.w;
        }
        for (int j = 4; j < cnt; j++) {
            const int p = g_order[start + j];
            const size_t o = (size_t)p * (CC / 4) + tx;
            const float4 xt = __ldcs(&f4[o]);
            const float4 yt = __ldcs(&f4[o + 8]);
            a0.x += xt.x; a0.y += xt.y; a0.z += xt.z; a0.w += xt.w;
            a1.x += yt.x; a1.y += yt.y; a1.z += yt.z; a1.w += yt.w;
        }
    }

    const float inv = 1.0f / (float)max(cnt, 1);
    a0.x *= inv; a0.y *= inv; a0.z *= inv; a0.w *= inv;
    a1.x *= inv; a1.y *= inv; a1.z *= inv; a1.w *= inv;

    __shared__ float sh[CC][33];
    sh[tx * 4 + 0][ty] = a0.x;
    sh[tx * 4 + 1][ty] = a0.y;
    sh[tx * 4 + 2][ty] = a0.z;
    sh[tx * 4 + 3][ty] = a0.w;
    sh[(tx + 8) * 4 + 0][ty] = a1.x;
    sh[(tx + 8) * 4 + 1][ty] = a1.y;
    sh[(tx + 8) * 4 + 2][ty] = a1.z;
    sh[(tx + 8) * 4 + 3][ty] = a1.w;
    __syncthreads();

    const int tid = ty * 8 + tx;
    const int lane = tid & 31;
    #pragma unroll
    for (int r = 0; r < 8; r++) {
        const int c = (tid >> 5) + r * 8;
        __stcs(&out[((size_t)b * CC + c) * R3 + v0 + lane], sh[c][lane]);
    }

    // reset counts for the next replay
    if (tid < 32) g_cnt[b * R3 + v0 + tid] = 0;
}

// ---------------------------------------------------------------------------
extern "C" void kernel_launch(void* const* d_in, const int* in_sizes, int n_in,
                              void* d_out, int out_size) {
    const float* features = (const float*)d_in[0];
    const float* coords   = (const float*)d_in[1];
    float* out = (float*)d_out;

    const size_t avg_elems = (size_t)BB * CC * R3;
    const size_t nc_elems  = (size_t)BB * NN * 3;
    const int write_nc = ((size_t)out_size >= avg_elems + nc_elems) ? 1 : 0;
    float* out_nc = out + avg_elems;

    k_mean1<<<BB * NPART, 256>>>(coords);
    k_maxnorm<<<BB * NPART, 256>>>(coords);
    k_points<<<BB * NN / 256, 256>>>(coords, out_nc, write_nc);
    k_scan3<<<BB * SCAN_BLKS, 256>>>();
    k_reorder<<<BB * NN / 256, 256>>>();
    {
        dim3 grid(R3 / 32, BB);
        dim3 block(8, 32);
        k_gather<<<grid, block>>>(features, out);
    }
}

// round 14
// speedup vs baseline: 1.4097x; 1.1527x over previous
#include <cuda_runtime.h>
#include <cuda_bf16.h>

#define BB 16
#define NN 32768
#define CC 64
#define RR 32
#define R3 (RR*RR*RR)
#define EPSF 1e-6f
#define NPART 32     // partial-reduction blocks per batch
#define SCAN_BLKS 32 // scan blocks per batch (each covers 1024 counts)

// Scratch (device globals — zero-initialized at load; no allocation allowed)
__device__ __align__(16) int g_cnt[BB * R3];    // points per voxel (re-zeroed by k_gather)
__device__ __align__(16) int g_cursor[BB * R3]; // reorder cursor (ends at start+cnt)
__device__ int   g_idx[BB * NN];        // voxel index per point
__device__ int   g_order[BB * NN];      // point ids grouped by voxel
__device__ float g_part[BB * NPART][3]; // partial coord sums
__device__ int   g_maxsq[BB];           // max squared norm, float bits (>=0)
__device__ int   g_bsum[BB * SCAN_BLKS];// per-scan-block count sums

// Deterministic mean recompute from partials (same order everywhere)
__device__ __forceinline__ void load_mean(int b, float m[3]) {
    float ax = 0.f, ay = 0.f, az = 0.f;
    #pragma unroll 4
    for (int p = 0; p < NPART; p++) {
        ax += g_part[b * NPART + p][0];
        ay += g_part[b * NPART + p][1];
        az += g_part[b * NPART + p][2];
    }
    m[0] = ax / (float)NN; m[1] = ay / (float)NN; m[2] = az / (float)NN;
}

// ---------------------------------------------------------------------------
__global__ void k_mean1(const float* __restrict__ coords) {
    const int bid = blockIdx.x;
    const int b = bid / NPART;
    const int part = bid % NPART;
    const int per = NN / NPART;
    const float* cb = coords + ((size_t)b * NN + (size_t)part * per) * 3;

    if (part == 0 && threadIdx.x == 0) g_maxsq[b] = 0;

    float sx = 0.f, sy = 0.f, sz = 0.f;
    for (int n = threadIdx.x; n < per; n += blockDim.x) {
        sx += cb[n * 3 + 0];
        sy += cb[n * 3 + 1];
        sz += cb[n * 3 + 2];
    }
    #pragma unroll
    for (int off = 16; off; off >>= 1) {
        sx += __shfl_down_sync(0xffffffffu, sx, off);
        sy += __shfl_down_sync(0xffffffffu, sy, off);
        sz += __shfl_down_sync(0xffffffffu, sz, off);
    }
    __shared__ float sh[3][8];
    const int lane = threadIdx.x & 31, w = threadIdx.x >> 5;
    if (lane == 0) { sh[0][w] = sx; sh[1][w] = sy; sh[2][w] = sz; }
    __syncthreads();
    if (threadIdx.x == 0) {
        float ax = 0.f, ay = 0.f, az = 0.f;
        const int nw = blockDim.x >> 5;
        for (int k = 0; k < nw; k++) { ax += sh[0][k]; ay += sh[1][k]; az += sh[2][k]; }
        g_part[bid][0] = ax; g_part[bid][1] = ay; g_part[bid][2] = az;
    }
}

// ---------------------------------------------------------------------------
__global__ void k_maxnorm(const float* __restrict__ coords) {
    const int bid = blockIdx.x;
    const int b = bid / NPART;
    const int part = bid % NPART;
    const int per = NN / NPART;
    const float* cb = coords + ((size_t)b * NN + (size_t)part * per) * 3;

    __shared__ float smean[3];
    if (threadIdx.x < 3) {
        float m[3];
        load_mean(b, m);
        smean[threadIdx.x] = m[threadIdx.x];
    }
    __syncthreads();
    const float mx = smean[0], my = smean[1], mz = smean[2];

    float m = 0.f;
    for (int n = threadIdx.x; n < per; n += blockDim.x) {
        float dx = cb[n * 3 + 0] - mx;
        float dy = cb[n * 3 + 1] - my;
        float dz = cb[n * 3 + 2] - mz;
        m = fmaxf(m, dx * dx + dy * dy + dz * dz);
    }
    #pragma unroll
    for (int off = 16; off; off >>= 1)
        m = fmaxf(m, __shfl_down_sync(0xffffffffu, m, off));
    __shared__ float sh[8];
    const int lane = threadIdx.x & 31, w = threadIdx.x >> 5;
    if (lane == 0) sh[w] = m;
    __syncthreads();
    if (threadIdx.x == 0) {
        const int nw = blockDim.x >> 5;
        for (int k = 0; k < nw; k++) m = fmaxf(m, sh[k]);
        atomicMax(&g_maxsq[b], __float_as_int(m));
    }
}

// ---------------------------------------------------------------------------
__global__ void k_points(const float* __restrict__ coords,
                         float* __restrict__ out_nc, int write_nc) {
    const int t = blockIdx.x * blockDim.x + threadIdx.x;
    const int b = t >> 15;

    __shared__ float smean[3];
    __shared__ float sden;
    if (threadIdx.x < 3) {
        float m[3];
        load_mean(b, m);
        smean[threadIdx.x] = m[threadIdx.x];
        if (threadIdx.x == 0)
            sden = __fmaf_rn(2.f, __fsqrt_rn(__int_as_float(g_maxsq[b])), EPSF);
    }
    __syncthreads();
    const float d = sden;
    const float mx = smean[0], my = smean[1], mz = smean[2];

    const float x = coords[(size_t)t * 3 + 0];
    const float y = coords[(size_t)t * 3 + 1];
    const float z = coords[(size_t)t * 3 + 2];

    const float nx = __fadd_rn(__fdiv_rn(__fsub_rn(x, mx), d), 0.5f);
    const float ny = __fadd_rn(__fdiv_rn(__fsub_rn(y, my), d), 0.5f);
    const float nz = __fadd_rn(__fdiv_rn(__fsub_rn(z, mz), d), 0.5f);

    int vx = __float2int_rn(__fmul_rn(nx, (float)(RR - 1)));
    int vy = __float2int_rn(__fmul_rn(ny, (float)(RR - 1)));
    int vz = __float2int_rn(__fmul_rn(nz, (float)(RR - 1)));
    vx = min(max(vx, 0), RR - 1);
    vy = min(max(vy, 0), RR - 1);
    vz = min(max(vz, 0), RR - 1);

    const int idx = vx * (RR * RR) + vy * RR + vz;
    g_idx[t] = idx;
    atomicAdd(&g_cnt[b * R3 + idx], 1);

    if (write_nc) {
        out_nc[(size_t)t * 3 + 0] = nx;
        out_nc[(size_t)t * 3 + 1] = ny;
        out_nc[(size_t)t * 3 + 2] = nz;
    }
}

// ---------------------------------------------------------------------------
__global__ void k_scan1() {
    const int4* c4 = reinterpret_cast<const int4*>(g_cnt);
    const int4 v = c4[blockIdx.x * 256 + threadIdx.x];
    int s = v.x + v.y + v.z + v.w;
    #pragma unroll
    for (int off = 16; off; off >>= 1)
        s += __shfl_down_sync(0xffffffffu, s, off);
    __shared__ int sh[8];
    const int lane = threadIdx.x & 31, w = threadIdx.x >> 5;
    if (lane == 0) sh[w] = s;
    __syncthreads();
    if (threadIdx.x == 0) {
        int t = 0;
        #pragma unroll
        for (int k = 0; k < 8; k++) t += sh[k];
        g_bsum[blockIdx.x] = t;
    }
}

// ---------------------------------------------------------------------------
__global__ void k_scan3() {
    const int batch = blockIdx.x >> 5;
    const int blk   = blockIdx.x & 31;

    __shared__ int sboff;
    if (threadIdx.x < 32) {
        int v = g_bsum[batch * SCAN_BLKS + threadIdx.x];
        int inc = v;
        #pragma unroll
        for (int off = 1; off < 32; off <<= 1) {
            int u = __shfl_up_sync(0xffffffffu, inc, off);
            if (threadIdx.x >= off) inc += u;
        }
        if (threadIdx.x == blk) sboff = batch * NN + inc - v;
    }

    const int4* c4 = reinterpret_cast<const int4*>(g_cnt);
    const int i4 = blockIdx.x * 256 + threadIdx.x;
    const int4 v = c4[i4];
    const int tsum = v.x + v.y + v.z + v.w;

    const int lane = threadIdx.x & 31, w = threadIdx.x >> 5;
    int inc = tsum;
    #pragma unroll
    for (int off = 1; off < 32; off <<= 1) {
        int u = __shfl_up_sync(0xffffffffu, inc, off);
        if (lane >= off) inc += u;
    }
    __shared__ int wsum[8];
    if (lane == 31) wsum[w] = inc;
    __syncthreads();
    int woff = 0;
    #pragma unroll
    for (int k = 0; k < 8; k++) woff += (k < w) ? wsum[k] : 0;

    int base = sboff + woff + inc - tsum;
    int4 cur;
    cur.x = base;
    cur.y = base + v.x;
    cur.z = cur.y + v.y;
    cur.w = cur.z + v.z;
    reinterpret_cast<int4*>(g_cursor)[i4] = cur;
}

// ---------------------------------------------------------------------------
__global__ void k_reorder() {
    const int t = blockIdx.x * blockDim.x + threadIdx.x;
    const int b = t >> 15;
    const int slot = atomicAdd(&g_cursor[b * R3 + g_idx[t]], 1);
    g_order[slot] = t;
}

// ---------------------------------------------------------------------------
// Fused gather + mean + transpose — R11 structure (best known), with
// __launch_bounds__(256, 6): 48 warps/SM resident (vs 32) to hide load
// latency. 4-point predicated pipelined head, rare scalar tail.
// Epilogue re-zeroes g_cnt for the next graph replay.
// ---------------------------------------------------------------------------
__global__ void __launch_bounds__(256, 6)
k_gather(const float* __restrict__ features, float* __restrict__ out) {
    const int b  = blockIdx.y;
    const int v0 = blockIdx.x * 32;
    const int tx = threadIdx.x;           // 0..7
    const int ty = threadIdx.y;           // 0..31
    const int seg = b * R3 + v0 + ty;

    const int cnt   = g_cnt[seg];
    const int start = g_cursor[seg] - cnt;
    const float4* f4 = reinterpret_cast<const float4*>(features);

    float4 a0 = make_float4(0.f, 0.f, 0.f, 0.f);
    float4 a1 = make_float4(0.f, 0.f, 0.f, 0.f);

    if (cnt > 0) {
        const bool h1 = cnt > 1, h2 = cnt > 2, h3 = cnt > 3;

        // --- level 1: up to 4 independent order loads (predicated) ---
        const int p0 = g_order[start];
        int p1 = 0, p2 = 0, p3 = 0;
        if (h1) p1 = g_order[start + 1];
        if (h2) p2 = g_order[start + 2];
        if (h3) p3 = g_order[start + 3];

        // --- level 2: up to 8 independent feature loads (predicated) ---
        const size_t o0 = (size_t)p0 * (CC / 4) + tx;
        const size_t o1 = (size_t)p1 * (CC / 4) + tx;
        const size_t o2 = (size_t)p2 * (CC / 4) + tx;
        const size_t o3 = (size_t)p3 * (CC / 4) + tx;
        float4 x1, y1, x2, y2, x3, y3;
        const float4 x0 = __ldcs(&f4[o0]);
        const float4 y0 = __ldcs(&f4[o0 + 8]);
        if (h1) { x1 = __ldcs(&f4[o1]); y1 = __ldcs(&f4[o1 + 8]); }
        if (h2) { x2 = __ldcs(&f4[o2]); y2 = __ldcs(&f4[o2 + 8]); }
        if (h3) { x3 = __ldcs(&f4[o3]); y3 = __ldcs(&f4[o3 + 8]); }

        // --- accumulate (guarded by the same predicates) ---
        a0.x = x0.x; a0.y = x0.y; a0.z = x0.z; a0.w = x0.w;
        a1.x = y0.x; a1.y = y0.y; a1.z = y0.z; a1.w = y0.w;
        if (h1) {
            a0.x += x1.x; a0.y += x1.y; a0.z += x1.z; a0.w += x1.w;
            a1.x += y1.x; a1.y += y1.y; a1.z += y1.z; a1.w += y1.w;
        }
        if (h2) {
            a0.x += x2.x; a0.y += x2.y; a0.z += x2.z; a0.w += x2.w;
            a1.x += y2.x; a1.y += y2.y; a1.z += y2.z; a1.w += y2.w;
        }
        if (h3) {
            a0.x += x3.x; a0.y += x3.y; a0.z += x3.z; a0.w += x3.w;
            a1.x += y3.x; a1.y += y3.y; a1.z += y3.z; a1.w += y3.w;
        }
        // rare tail (P(cnt>4) ~ 0.4% at Poisson(1))
        for (int j = 4; j < cnt; j++) {
            const int p = g_order[start + j];
            const size_t o = (size_t)p * (CC / 4) + tx;
            const float4 xt = __ldcs(&f4[o]);
            const float4 yt = __ldcs(&f4[o + 8]);
            a0.x += xt.x; a0.y += xt.y; a0.z += xt.z; a0.w += xt.w;
            a1.x += yt.x; a1.y += yt.y; a1.z += yt.z; a1.w += yt.w;
        }
    }

    const float inv = 1.0f / (float)max(cnt, 1);
    a0.x *= inv; a0.y *= inv; a0.z *= inv; a0.w *= inv;
    a1.x *= inv; a1.y *= inv; a1.z *= inv; a1.w *= inv;

    __shared__ float sh[CC][33];
    sh[tx * 4 + 0][ty] = a0.x;
    sh[tx * 4 + 1][ty] = a0.y;
    sh[tx * 4 + 2][ty] = a0.z;
    sh[tx * 4 + 3][ty] = a0.w;
    sh[(tx + 8) * 4 + 0][ty] = a1.x;
    sh[(tx + 8) * 4 + 1][ty] = a1.y;
    sh[(tx + 8) * 4 + 2][ty] = a1.z;
    sh[(tx + 8) * 4 + 3][ty] = a1.w;
    __syncthreads();

    const int tid = ty * 8 + tx;
    const int lane = tid & 31;
    #pragma unroll
    for (int r = 0; r < 8; r++) {
        const int c = (tid >> 5) + r * 8;
        __stcs(&out[((size_t)b * CC + c) * R3 + v0 + lane], sh[c][lane]);
    }

    // reset counts for the next replay
    if (tid < 32) g_cnt[b * R3 + v0 + tid] = 0;
}

// ---------------------------------------------------------------------------
extern "C" void kernel_launch(void* const* d_in, const int* in_sizes, int n_in,
                              void* d_out, int out_size) {
    const float* features = (const float*)d_in[0];
    const float* coords   = (const float*)d_in[1];
    float* out = (float*)d_out;

    const size_t avg_elems = (size_t)BB * CC * R3;
    const size_t nc_elems  = (size_t)BB * NN * 3;
    const int write_nc = ((size_t)out_size >= avg_elems + nc_elems) ? 1 : 0;
    float* out_nc = out + avg_elems;

    k_mean1<<<BB * NPART, 256>>>(coords);
    k_maxnorm<<<BB * NPART, 256>>>(coords);
    k_points<<<BB * NN / 256, 256>>>(coords, out_nc, write_nc);
    k_scan1<<<BB * SCAN_BLKS, 256>>>();
    k_scan3<<<BB * SCAN_BLKS, 256>>>();
    k_reorder<<<BB * NN / 256, 256>>>();
    {
        dim3 grid(R3 / 32, BB);
        dim3 block(8, 32);
        k_gather<<<grid, block>>>(features, out);
    }
}